// round 7
// baseline (speedup 1.0000x reference)
#include <cuda_runtime.h>
#include <cstdint>

#define Bx 16
#define Sx 512
#define Dx 512
#define Lx 64

typedef unsigned long long u64;

// scratch (device globals; no runtime allocation)
__device__ float f_g[Bx * Sx * Dx];   // 16 MB feature rows
__device__ int   cls_g[Bx * Sx];
__device__ float si_g[Bx * Sx];
__device__ float sj_g[Bx * Sx];
__device__ float u_g[Dx];
__device__ float v_g[Dx];
__device__ float c_g;

// ---------------------------------------------------------------------------
// Setup kernel 1: embedding gather + logits + cls argmax (first occurrence)
// ---------------------------------------------------------------------------
__global__ void k_embed(const int* __restrict__ tok, const float* __restrict__ emb,
                        const float* __restrict__ posW, const float* __restrict__ posb)
{
    int bs  = blockIdx.x;          // 0 .. B*S-1
    int tid = threadIdx.x;         // 128 threads
    __shared__ float fs[Dx];
    __shared__ float lg[Lx];

    int t = tok[bs];
    float4 v4 = ((const float4*)(emb + (size_t)t * Dx))[tid];
    ((float4*)(f_g + (size_t)bs * Dx))[tid] = v4;
    ((float4*)fs)[tid] = v4;
    __syncthreads();

    if (tid < Lx) {
        float acc = 0.f;
        #pragma unroll 8
        for (int d = 0; d < Dx; d++) acc = fmaf(fs[d], posW[d * Lx + tid], acc);
        lg[tid] = acc + posb[tid];
    }
    __syncthreads();

    if (tid == 0) {
        float bv = lg[0]; int bi = 0;
        for (int l = 1; l < Lx; l++) { float x = lg[l]; if (x > bv) { bv = x; bi = l; } }
        cls_g[bs] = bi;
    }
}

// ---------------------------------------------------------------------------
// Setup kernel 2: u = W1a @ w2, v = W1b @ w2, c = b1 @ w2 + b2
// ---------------------------------------------------------------------------
__global__ void k_uvc(const float* __restrict__ W1, const float* __restrict__ b1,
                      const float* __restrict__ w2, const float* __restrict__ b2)
{
    int o   = blockIdx.x;          // 0..1024 (512 u, 512 v, 1 c)
    int tid = threadIdx.x;         // 128
    __shared__ float red[128];
    const float* row = (o < 1024) ? (W1 + (size_t)o * Dx) : b1;
    float acc = 0.f;
    for (int k = tid; k < Dx; k += 128) acc = fmaf(row[k], w2[k], acc);
    red[tid] = acc; __syncthreads();
    for (int s = 64; s >= 1; s >>= 1) { if (tid < s) red[tid] += red[tid + s]; __syncthreads(); }
    if (tid == 0) {
        if      (o < 512)  u_g[o]       = red[0];
        else if (o < 1024) v_g[o - 512] = red[0];
        else               c_g          = red[0] + b2[0];
    }
}

// ---------------------------------------------------------------------------
// Setup kernel 3: initial si = f @ u, sj = f @ v
// ---------------------------------------------------------------------------
__global__ void k_sisj()
{
    int bs = blockIdx.x; int tid = threadIdx.x;  // 128
    __shared__ float ru[128], rv[128];
    const float* frow = f_g + (size_t)bs * Dx;
    float au = 0.f, av = 0.f;
    for (int k = tid; k < Dx; k += 128) {
        float fv = frow[k];
        au = fmaf(fv, u_g[k], au);
        av = fmaf(fv, v_g[k], av);
    }
    ru[tid] = au; rv[tid] = av; __syncthreads();
    for (int s = 64; s >= 1; s >>= 1) {
        if (tid < s) { ru[tid] += ru[tid + s]; rv[tid] += rv[tid + s]; }
        __syncthreads();
    }
    if (tid == 0) { si_g[bs] = ru[0]; sj_g[bs] = rv[0]; }
}

// jnp.argmax semantics: NaN is maximal; ties (incl. NaN-vs-NaN) -> lowest flat index
__device__ __forceinline__ bool better(float v1, int k1, float v2, int k2)
{
    bool n1 = (v1 != v1), n2 = (v2 != v2);
    if (n1 | n2) { if (n1 && n2) return k1 < k2; return n1; }
    if (v1 != v2) return v1 > v2;
    return k1 < k2;
}

// ---------------------------------------------------------------------------
// Main persistent kernel: one block per batch, 511 sequential merge steps
// ---------------------------------------------------------------------------
__global__ void __launch_bounds__(512, 1) k_parse(const float* __restrict__ W1,
                                                  const float* __restrict__ b1,
                                                  float* __restrict__ out)
{
    __shared__ u64   adjw[Sx][8];        // 32 KB adjacency bitmasks
    __shared__ float si[Sx], sj[Sx];
    __shared__ float fi[Sx], fj[Sx];
    __shared__ float us[Sx], vs[Sx];
    __shared__ float dotU[128], dotV[128];
    __shared__ float wv[16]; __shared__ int wk[16];
    __shared__ u64   rowbuf[8];
    __shared__ float sel_v; __shared__ int sel_k; __shared__ float totsh;

    const float NEG = __int_as_float(0xff800000);   // -inf
    int b = blockIdx.x, tid = threadIdx.x;
    size_t fbase = (size_t)b * Sx * Dx;

    si[tid] = si_g[b * Sx + tid];
    sj[tid] = sj_g[b * Sx + tid];
    us[tid] = u_g[tid];
    vs[tid] = v_g[tid];
    ((int*)fi)[tid] = cls_g[b * Sx + tid];   // borrow fi as int staging for cls
    if (tid == 0) totsh = 0.f;
    __syncthreads();

    // build adjacency: (|i-j|==1 | cls_i==cls_j) & i!=j
    {
        const int* cl = (const int*)fi;
        int myc = cl[tid];
        #pragma unroll
        for (int w = 0; w < 8; w++) {
            u64 m = 0;
            for (int bb = 0; bb < 64; bb++) {
                int j = (w << 6) + bb;
                bool a = (j != tid) && ((j == tid + 1) || (j + 1 == tid) || (cl[j] == myc));
                m |= ((u64)a) << bb;
            }
            adjw[tid][w] = m;
        }
    }
    __syncthreads();

    const float C = c_g;
    float* tree = out + Bx + (size_t)b * (Sx - 1) * 2;
    int lane = tid & 31, wid = tid >> 5;

    for (int step = 0; step < Sx - 1; step++) {
        // ---- 1. sparse masked argmax over sc[i,j] = si[i]+sj[j]+c ----
        float bv = NEG; int bk = 0x7fffffff;
        float sir = si[tid];
        #pragma unroll
        for (int w = 0; w < 8; w++) {
            u64 m = adjw[tid][w];
            while (m) {
                int bb = __ffsll((long long)m) - 1;
                m &= m - 1;
                int j = (w << 6) + bb;
                float v = (sir + sj[j]) + C;
                int kk = (tid << 9) + j;
                if (better(v, kk, bv, bk)) { bv = v; bk = kk; }
            }
        }
        #pragma unroll
        for (int off = 16; off; off >>= 1) {
            float ov = __shfl_down_sync(0xffffffffu, bv, off);
            int   ok = __shfl_down_sync(0xffffffffu, bk, off);
            if (better(ov, ok, bv, bk)) { bv = ov; bk = ok; }
        }
        if (lane == 0) { wv[wid] = bv; wk[wid] = bk; }
        __syncthreads();
        if (tid < 32) {
            float v = (tid < 16) ? wv[tid] : NEG;
            int   k = (tid < 16) ? wk[tid] : 0x7fffffff;
            #pragma unroll
            for (int off = 8; off; off >>= 1) {
                float ov = __shfl_down_sync(0xffffffffu, v, off);
                int   ok = __shfl_down_sync(0xffffffffu, k, off);
                if (better(ov, ok, v, k)) { v = ov; k = ok; }
            }
            if (tid == 0) {
                if (!(v != v) && v == NEG) k = 0;   // all entries -inf -> flat index 0
                sel_v = v; sel_k = k;
            }
        }
        __syncthreads();

        int sel = sel_k; float best = sel_v;
        int i = sel >> 9, j = sel & 511;
        if (tid == 0) {
            totsh += best;
            tree[step * 2]     = (float)i;
            tree[step * 2 + 1] = (float)j;
        }

        // ---- 2. snapshot merged adjacency row; stage f_i, f_j ----
        if (tid < 8) rowbuf[tid] = adjw[i][tid] | adjw[j][tid];
        fi[tid] = f_g[fbase + (size_t)i * Dx + tid];
        fj[tid] = f_g[fbase + (size_t)j * Dx + tid];
        __syncthreads();

        // ---- 3. adjacency update (matches reference .at[] op order) ----
        {
            int r = tid;
            int wi = i >> 6, wj = j >> 6;
            u64 mi = 1ull << (i & 63), mj = 1ull << (j & 63);
            if (r == j) {
                #pragma unroll
                for (int w = 0; w < 8; w++) adjw[r][w] = 0ull;
            } else if (r == i) {
                #pragma unroll
                for (int w = 0; w < 8; w++) {
                    u64 m = rowbuf[w];
                    if (w == wi) m &= ~mi;
                    if (w == wj) m &= ~mj;
                    adjw[r][w] = m;
                }
            } else {
                u64 m = adjw[r][wi];
                if ((rowbuf[r >> 6] >> (r & 63)) & 1ull) m |= mi; else m &= ~mi;
                adjw[r][wi] = m;
                u64 m2 = adjw[r][wj] & ~mj;
                adjw[r][wj] = m2;
            }
        }

        // ---- 4. parent = f_i @ W1a + f_j @ W1b + b1 (fp32 gemv) ----
        int q = tid >> 2, kc = tid & 3;     // q: d-quad 0..127, kc: k-chunk 0..3
        float4 aA = make_float4(0.f, 0.f, 0.f, 0.f);
        float4 aB = make_float4(0.f, 0.f, 0.f, 0.f);
        {
            const float* pA = W1 + (size_t)(kc * 128) * Dx + 4 * q;
            const float* pB = pA + (size_t)Dx * Dx;
            int kbase = kc * 128;
            #pragma unroll 8
            for (int kk2 = 0; kk2 < 128; kk2++) {
                float fik = fi[kbase + kk2], fjk = fj[kbase + kk2];
                float4 wa = *(const float4*)(pA + (size_t)kk2 * Dx);
                float4 wb = *(const float4*)(pB + (size_t)kk2 * Dx);
                aA.x = fmaf(fik, wa.x, aA.x); aA.y = fmaf(fik, wa.y, aA.y);
                aA.z = fmaf(fik, wa.z, aA.z); aA.w = fmaf(fik, wa.w, aA.w);
                aB.x = fmaf(fjk, wb.x, aB.x); aB.y = fmaf(fjk, wb.y, aB.y);
                aB.z = fmaf(fjk, wb.z, aB.z); aB.w = fmaf(fjk, wb.w, aB.w);
            }
        }
        #pragma unroll
        for (int off = 1; off <= 2; off <<= 1) {   // reduce the 4 k-chunks (adjacent lanes)
            aA.x += __shfl_xor_sync(0xffffffffu, aA.x, off);
            aA.y += __shfl_xor_sync(0xffffffffu, aA.y, off);
            aA.z += __shfl_xor_sync(0xffffffffu, aA.z, off);
            aA.w += __shfl_xor_sync(0xffffffffu, aA.w, off);
            aB.x += __shfl_xor_sync(0xffffffffu, aB.x, off);
            aB.y += __shfl_xor_sync(0xffffffffu, aB.y, off);
            aB.z += __shfl_xor_sync(0xffffffffu, aB.z, off);
            aB.w += __shfl_xor_sync(0xffffffffu, aB.w, off);
        }
        if (kc == 0) {
            float4 b4 = *(const float4*)(b1 + 4 * q);
            float4 par;
            par.x = (aA.x + aB.x) + b4.x;
            par.y = (aA.y + aB.y) + b4.y;
            par.z = (aA.z + aB.z) + b4.z;
            par.w = (aA.w + aB.w) + b4.w;
            *(float4*)(f_g + fbase + (size_t)i * Dx + 4 * q) = par;
            float du = fmaf(par.w, us[4*q+3], fmaf(par.z, us[4*q+2], fmaf(par.y, us[4*q+1], par.x * us[4*q])));
            float dv = fmaf(par.w, vs[4*q+3], fmaf(par.z, vs[4*q+2], fmaf(par.y, vs[4*q+1], par.x * vs[4*q])));
            dotU[q] = du; dotV[q] = dv;
        }
        __syncthreads();
        #pragma unroll
        for (int s2 = 64; s2 >= 1; s2 >>= 1) {
            if (tid < s2) { dotU[tid] += dotU[tid + s2]; dotV[tid] += dotV[tid + s2]; }
            __syncthreads();
        }
        if (tid == 0) { si[i] = dotU[0]; sj[i] = dotV[0]; }
        __syncthreads();
    }

    if (tid == 0) out[b] = totsh;
}

// ---------------------------------------------------------------------------
extern "C" void kernel_launch(void* const* d_in, const int* in_sizes, int n_in,
                              void* d_out, int out_size)
{
    const int*   tok  = (const int*)  d_in[0];   // token_ids (B,S) int32
    const float* emb  = (const float*)d_in[1];   // vocab_emb (V,D)
    const float* posW = (const float*)d_in[2];   // pos_W (D,L)
    const float* posb = (const float*)d_in[3];   // pos_b (L,)
    const float* W1   = (const float*)d_in[4];   // W1 (2D,D)
    const float* b1   = (const float*)d_in[5];   // b1 (D,)
    const float* w2   = (const float*)d_in[6];   // w2 (D,)
    const float* b2   = (const float*)d_in[7];   // b2 ()
    float* out = (float*)d_out;                  // [B scores][B*(S-1)*2 tree]

    k_embed<<<Bx * Sx, 128>>>(tok, emb, posW, posb);
    k_uvc  <<<2 * Dx + 1, 128>>>(W1, b1, w2, b2);
    k_sisj <<<Bx * Sx, 128>>>();
    k_parse<<<Bx, 512>>>(W1, b1, out);
}

// round 9
// speedup vs baseline: 2.4764x; 2.4764x over previous
#include <cuda_runtime.h>
#include <cstdint>

#define Bx 16
#define Sx 512
#define Dx 512
#define Lx 64
#define CLU 8          // CTAs per cluster (per batch)
#define DSL 64         // output dims per CTA (512/8)

typedef unsigned long long u64;

// scratch (device globals; no runtime allocation)
__device__ float f_g[Bx * Sx * Dx];   // 16 MB feature rows
__device__ int   cls_g[Bx * Sx];
__device__ float si_g[Bx * Sx];
__device__ float sj_g[Bx * Sx];
__device__ float u_g[Dx];
__device__ float v_g[Dx];
__device__ float c_g;

// ---------------------------------------------------------------------------
// Setup kernel 1: embedding gather + logits + cls argmax (first occurrence)
// ---------------------------------------------------------------------------
__global__ void k_embed(const int* __restrict__ tok, const float* __restrict__ emb,
                        const float* __restrict__ posW, const float* __restrict__ posb)
{
    int bs  = blockIdx.x;          // 0 .. B*S-1
    int tid = threadIdx.x;         // 128 threads
    __shared__ float fs[Dx];
    __shared__ float lg[Lx];

    int t = tok[bs];
    float4 v4 = ((const float4*)(emb + (size_t)t * Dx))[tid];
    ((float4*)(f_g + (size_t)bs * Dx))[tid] = v4;
    ((float4*)fs)[tid] = v4;
    __syncthreads();

    if (tid < Lx) {
        float acc = 0.f;
        #pragma unroll 8
        for (int d = 0; d < Dx; d++) acc = fmaf(fs[d], posW[d * Lx + tid], acc);
        lg[tid] = acc + posb[tid];
    }
    __syncthreads();

    if (tid == 0) {
        float bv = lg[0]; int bi = 0;
        for (int l = 1; l < Lx; l++) { float x = lg[l]; if (x > bv) { bv = x; bi = l; } }
        cls_g[bs] = bi;
    }
}

// ---------------------------------------------------------------------------
// Setup kernel 2: u = W1a @ w2, v = W1b @ w2, c = b1 @ w2 + b2
// ---------------------------------------------------------------------------
__global__ void k_uvc(const float* __restrict__ W1, const float* __restrict__ b1,
                      const float* __restrict__ w2, const float* __restrict__ b2)
{
    int o   = blockIdx.x;          // 0..1024 (512 u, 512 v, 1 c)
    int tid = threadIdx.x;         // 128
    __shared__ float red[128];
    const float* row = (o < 1024) ? (W1 + (size_t)o * Dx) : b1;
    float acc = 0.f;
    for (int k = tid; k < Dx; k += 128) acc = fmaf(row[k], w2[k], acc);
    red[tid] = acc; __syncthreads();
    for (int s = 64; s >= 1; s >>= 1) { if (tid < s) red[tid] += red[tid + s]; __syncthreads(); }
    if (tid == 0) {
        if      (o < 512)  u_g[o]       = red[0];
        else if (o < 1024) v_g[o - 512] = red[0];
        else               c_g          = red[0] + b2[0];
    }
}

// ---------------------------------------------------------------------------
// Setup kernel 3: initial si = f @ u, sj = f @ v
// ---------------------------------------------------------------------------
__global__ void k_sisj()
{
    int bs = blockIdx.x; int tid = threadIdx.x;  // 128
    __shared__ float ru[128], rv[128];
    const float* frow = f_g + (size_t)bs * Dx;
    float au = 0.f, av = 0.f;
    for (int k = tid; k < Dx; k += 128) {
        float fv = frow[k];
        au = fmaf(fv, u_g[k], au);
        av = fmaf(fv, v_g[k], av);
    }
    ru[tid] = au; rv[tid] = av; __syncthreads();
    for (int s = 64; s >= 1; s >>= 1) {
        if (tid < s) { ru[tid] += ru[tid + s]; rv[tid] += rv[tid + s]; }
        __syncthreads();
    }
    if (tid == 0) { si_g[bs] = ru[0]; sj_g[bs] = rv[0]; }
}

// jnp.argmax semantics: NaN is maximal; ties (incl. NaN-vs-NaN) -> lowest flat index
__device__ __forceinline__ bool better(float v1, int k1, float v2, int k2)
{
    bool n1 = (v1 != v1), n2 = (v2 != v2);
    if (n1 | n2) { if (n1 && n2) return k1 < k2; return n1; }
    if (v1 != v2) return v1 > v2;
    return k1 < k2;
}

__device__ __forceinline__ uint32_t smem_u32(const void* p)
{
    uint32_t a;
    asm("{ .reg .u64 t; cvta.to.shared.u64 t, %1; cvt.u32.u64 %0, t; }" : "=r"(a) : "l"(p));
    return a;
}

#define CLUSTER_ARRIVE() asm volatile("barrier.cluster.arrive.aligned;" ::: "memory")
#define CLUSTER_WAIT()   asm volatile("barrier.cluster.wait.aligned;"   ::: "memory")

// ---------------------------------------------------------------------------
// Main persistent kernel: 8-CTA cluster per batch. Control state (argmax,
// adjacency, si/sj) fully replicated per CTA; gemv split over output dims.
// ---------------------------------------------------------------------------
__global__ void __launch_bounds__(512, 1) __cluster_dims__(CLU, 1, 1)
k_parse(const float* __restrict__ W1, const float* __restrict__ b1,
        float* __restrict__ out)
{
    __shared__ u64    adjw[Sx][8];        // 32 KB adjacency bitmasks (replicated)
    __shared__ float  si[Sx], sj[Sx];
    __shared__ float  fi[Sx], fj[Sx];
    __shared__ float  us_s[DSL], vs_s[DSL];
    __shared__ float2 psum[16][32];       // gemv k-chunk partials (4 KB)
    __shared__ float2 part[CLU];          // cross-CTA dotU/dotV partials (DSMEM target)
    __shared__ float  wv[16]; __shared__ int wk[16];
    __shared__ u64    rowbuf[8];
    __shared__ float  sel_v; __shared__ int sel_k; __shared__ float totsh;

    const float NEG = __int_as_float(0xff800000);   // -inf
    int tid  = threadIdx.x;
    int b    = blockIdx.x >> 3;
    uint32_t rank;
    asm("mov.u32 %0, %%cluster_ctarank;" : "=r"(rank));
    size_t fbase = (size_t)b * Sx * Dx;
    int dbase = rank * DSL;

    si[tid] = si_g[b * Sx + tid];
    sj[tid] = sj_g[b * Sx + tid];
    if (tid < DSL) { us_s[tid] = u_g[dbase + tid]; vs_s[tid] = v_g[dbase + tid]; }
    ((int*)fi)[tid] = cls_g[b * Sx + tid];   // borrow fi as int staging for cls
    if (tid == 0) totsh = 0.f;
    __syncthreads();

    // build adjacency: (|i-j|==1 | cls_i==cls_j) & i!=j
    {
        const int* cl = (const int*)fi;
        int myc = cl[tid];
        #pragma unroll
        for (int w = 0; w < 8; w++) {
            u64 m = 0;
            for (int bb = 0; bb < 64; bb++) {
                int j = (w << 6) + bb;
                bool a = (j != tid) && ((j == tid + 1) || (j + 1 == tid) || (cl[j] == myc));
                m |= ((u64)a) << bb;
            }
            adjw[tid][w] = m;
        }
    }
    __syncthreads();

    const float C = c_g;
    float* tree = out + Bx + (size_t)b * (Sx - 1) * 2;
    int lane = tid & 31, wid = tid >> 5;
    uint32_t part_addr = smem_u32(&part[rank]);

    for (int step = 0; step < Sx - 1; step++) {
        // ---- 1. sparse masked argmax over sc[i,j] = si[i]+sj[j]+c (replicated) ----
        float bv = NEG; int bk = 0x7fffffff;
        float sir = si[tid];
        #pragma unroll
        for (int w = 0; w < 8; w++) {
            u64 m = adjw[tid][w];
            while (m) {
                int bb = __ffsll((long long)m) - 1;
                m &= m - 1;
                int j = (w << 6) + bb;
                float v = (sir + sj[j]) + C;
                int kk = (tid << 9) + j;
                if (better(v, kk, bv, bk)) { bv = v; bk = kk; }
            }
        }
        #pragma unroll
        for (int off = 16; off; off >>= 1) {
            float ov = __shfl_down_sync(0xffffffffu, bv, off);
            int   ok = __shfl_down_sync(0xffffffffu, bk, off);
            if (better(ov, ok, bv, bk)) { bv = ov; bk = ok; }
        }
        if (lane == 0) { wv[wid] = bv; wk[wid] = bk; }
        __syncthreads();
        if (tid < 32) {
            float v = (tid < 16) ? wv[tid] : NEG;
            int   k = (tid < 16) ? wk[tid] : 0x7fffffff;
            #pragma unroll
            for (int off = 8; off; off >>= 1) {
                float ov = __shfl_down_sync(0xffffffffu, v, off);
                int   ok = __shfl_down_sync(0xffffffffu, k, off);
                if (better(ov, ok, v, k)) { v = ov; k = ok; }
            }
            if (tid == 0) {
                if (!(v != v) && v == NEG) k = 0;   // all entries -inf -> flat index 0
                sel_v = v; sel_k = k;
            }
        }
        __syncthreads();

        int sel = sel_k; float best = sel_v;
        int i = sel >> 9, j = sel & 511;
        if (rank == 0 && tid == 0) {
            totsh += best;
            tree[step * 2]     = (float)i;
            tree[step * 2 + 1] = (float)j;
        }

        // ---- 2. snapshot merged adjacency row; stage f_i, f_j (L2, bypass L1) ----
        if (tid < 8) rowbuf[tid] = adjw[i][tid] | adjw[j][tid];
        fi[tid] = __ldcg(f_g + fbase + (size_t)i * Dx + tid);
        fj[tid] = __ldcg(f_g + fbase + (size_t)j * Dx + tid);
        __syncthreads();
        CLUSTER_ARRIVE();     // all my f_g reads of row i are done

        // ---- 3. adjacency update (local, replicated; matches reference .at[] order) ----
        {
            int r = tid;
            int wi = i >> 6, wj = j >> 6;
            u64 mi = 1ull << (i & 63), mj = 1ull << (j & 63);
            if (r == j) {
                #pragma unroll
                for (int w = 0; w < 8; w++) adjw[r][w] = 0ull;
            } else if (r == i) {
                #pragma unroll
                for (int w = 0; w < 8; w++) {
                    u64 m = rowbuf[w];
                    if (w == wi) m &= ~mi;
                    if (w == wj) m &= ~mj;
                    adjw[r][w] = m;
                }
            } else {
                u64 m = adjw[r][wi];
                if ((rowbuf[r >> 6] >> (r & 63)) & 1ull) m |= mi; else m &= ~mi;
                adjw[r][wi] = m;
                u64 m2 = adjw[r][wj] & ~mj;
                adjw[r][wj] = m2;
            }
        }

        // ---- 4. parent slice: 64 outputs per CTA ----
        // thread layout: d2 = tid&31 (float2 within slice), kc = tid>>5 (16 k-chunks of 32)
        {
            int d2 = tid & 31, kc = tid >> 5;
            int kb = kc * 32;
            const float* pA = W1 + (size_t)kb * Dx + dbase + 2 * d2;
            const float* pB = pA + (size_t)Dx * Dx;
            float ax = 0.f, ay = 0.f;
            #pragma unroll 8
            for (int kk2 = 0; kk2 < 32; kk2++) {
                float fik = fi[kb + kk2], fjk = fj[kb + kk2];
                float2 wa = *(const float2*)(pA + (size_t)kk2 * Dx);
                float2 wb = *(const float2*)(pB + (size_t)kk2 * Dx);
                ax = fmaf(fjk, wb.x, fmaf(fik, wa.x, ax));
                ay = fmaf(fjk, wb.y, fmaf(fik, wa.y, ay));
            }
            psum[kc][d2] = make_float2(ax, ay);
        }
        __syncthreads();
        CLUSTER_WAIT();       // every CTA finished reading old f_g row i

        if (tid < 32) {
            float sx = 0.f, sy = 0.f;
            #pragma unroll
            for (int w = 0; w < 16; w++) { float2 p = psum[w][tid]; sx += p.x; sy += p.y; }
            int dl = 2 * tid;                 // local dim within slice
            float px = sx + b1[dbase + dl];
            float py = sy + b1[dbase + dl + 1];
            __stcg((float2*)(f_g + fbase + (size_t)i * Dx + dbase + dl), make_float2(px, py));
            float du = fmaf(py, us_s[dl + 1], px * us_s[dl]);
            float dv = fmaf(py, vs_s[dl + 1], px * vs_s[dl]);
            #pragma unroll
            for (int off = 16; off; off >>= 1) {
                du += __shfl_xor_sync(0xffffffffu, du, off);
                dv += __shfl_xor_sync(0xffffffffu, dv, off);
            }
            if (tid == 0) {
                float2 p2 = make_float2(du, dv);
                u64 pv; memcpy(&pv, &p2, 8);
                #pragma unroll
                for (int r = 0; r < CLU; r++) {
                    uint32_t ra;
                    asm volatile("mapa.shared::cluster.u32 %0, %1, %2;"
                                 : "=r"(ra) : "r"(part_addr), "r"(r));
                    asm volatile("st.shared::cluster.b64 [%0], %1;"
                                 :: "r"(ra), "l"(pv) : "memory");
                }
            }
        }

        // full cluster barrier: f_g slice writes + DSMEM partials visible everywhere
        CLUSTER_ARRIVE();
        CLUSTER_WAIT();

        if (tid == 0) {
            float sU = 0.f, sV = 0.f;
            #pragma unroll
            for (int r = 0; r < CLU; r++) { sU += part[r].x; sV += part[r].y; }
            si[i] = sU; sj[i] = sV;
        }
        __syncthreads();
    }

    if (rank == 0 && tid == 0) out[b] = totsh;
}

// ---------------------------------------------------------------------------
extern "C" void kernel_launch(void* const* d_in, const int* in_sizes, int n_in,
                              void* d_out, int out_size)
{
    const int*   tok  = (const int*)  d_in[0];   // token_ids (B,S) int32
    const float* emb  = (const float*)d_in[1];   // vocab_emb (V,D)
    const float* posW = (const float*)d_in[2];   // pos_W (D,L)
    const float* posb = (const float*)d_in[3];   // pos_b (L,)
    const float* W1   = (const float*)d_in[4];   // W1 (2D,D)
    const float* b1   = (const float*)d_in[5];   // b1 (D,)
    const float* w2   = (const float*)d_in[6];   // w2 (D,)
    const float* b2   = (const float*)d_in[7];   // b2 ()
    float* out = (float*)d_out;                  // [B scores][B*(S-1)*2 tree]

    k_embed<<<Bx * Sx, 128>>>(tok, emb, posW, posb);
    k_uvc  <<<2 * Dx + 1, 128>>>(W1, b1, w2, b2);
    k_sisj <<<Bx * Sx, 128>>>();
    k_parse<<<Bx * CLU, 512>>>(W1, b1, out);
}